// round 5
// baseline (speedup 1.0000x reference)
#include <cuda_runtime.h>

// BoxLoss: 3-scale YOLO box loss. ONE launch, ONE block (1024 threads).
// Total real work: 4800 (image,scale,target) tasks + <=50-cell gathers.
// All cross-SM coordination eliminated: keys, dup-check, group accumulators,
// and the final reduction all live in shared memory on a single SM.
// Group sums use integer fixed-point smem atomics -> associative -> exact
// and deterministic regardless of scheduling.

#define NT   50      // targets per image
#define NA   3       // anchors per scale
#define NC   85      // channels per cell
#define BMAX 32
#define NG   (BMAX * 3)          // 96 (image,scale) groups
#define TASKS_MAX (NG * NT)      // 4800
#define THRESH 0.5f
#define NTHREADS 1024
#define FIXSCALE 1073741824.0    // 2^30

__global__ void __launch_bounds__(NTHREADS, 1)
box_loss_single(const float* __restrict__ out0, const float* __restrict__ anc0,
                const float* __restrict__ out1, const float* __restrict__ anc1,
                const float* __restrict__ out2, const float* __restrict__ anc2,
                const float* __restrict__ targets,
                float* __restrict__ result, int B, float invB)
{
    const int tid   = threadIdx.x;
    const int total = B * 3 * NT;

    __shared__ int                skey[TASKS_MAX];
    __shared__ unsigned long long ssum[NG];
    __shared__ int                scnt[NG];
    __shared__ float              sgl[NG];

    if (tid < NG) { ssum[tid] = 0ull; scnt[tid] = 0; }

    // ---- preload all 18 anchor floats (uniform -> broadcast loads) ----
    float aw[3][NA], ah[3][NA];
    #pragma unroll
    for (int s = 0; s < 3; s++) {
        const float* a = (s == 0) ? anc0 : (s == 1) ? anc1 : anc2;
        #pragma unroll
        for (int i = 0; i < NA; i++) {
            aw[s][i] = __ldg(a + 2 * i);
            ah[s][i] = __ldg(a + 2 * i + 1);
        }
    }

    // ---- phase 1: per-task anchor assignment -> keys in smem ----
    #pragma unroll 5
    for (int t = tid; t < total; t += NTHREADS) {
        const int gi = t / NT, l = t - gi * NT;
        const int b  = gi / 3, g = gi - b * 3;
        const int G  = (g == 0) ? 52 : (g == 1) ? 26 : 13;

        const float* tg = targets + ((size_t)b * NT + l) * 5;
        const float x = __ldg(tg + 1), y = __ldg(tg + 2);
        const float w = __ldg(tg + 3), h = __ldg(tg + 4);
        const bool valid = !(x == 0.f && y == 0.f && w == 0.f && h == 0.f);

        const float fG = (float)G;
        const float tx = x * fG, ty = y * fG, tw = w * fG, th = h * fG;
        const float cx = floorf(tx), cy = floorf(ty);
        const int   icx = (int)cx, icy = (int)cy;
        const bool  inb = valid && icx >= 0 && icx < G && icy >= 0 && icy < G;

        // target rect; areas from rect diffs (matches reference numerics)
        const float zx = tx - cx - 0.5f, zy = ty - cy - 0.5f;
        const float t0 = zx - tw * 0.5f, t1 = zy - th * 0.5f;
        const float t2 = zx + tw * 0.5f, t3 = zy + th * 0.5f;
        const float area_t = (t2 - t0) * (t3 - t1);

        float overlap = -1.f;
        int   best = 0;
        #pragma unroll
        for (int a = 0; a < NA; a++) {
            const float w2 = aw[g][a] * 0.5f, h2 = ah[g][a] * 0.5f;
            const float x0 = fmaxf(t0, -w2), y0 = fmaxf(t1, -h2);
            const float x1 = fminf(t2,  w2), y1 = fminf(t3,  h2);
            const float inter  = (x0 < x1 && y0 < y1) ? (x1 - x0) * (y1 - y0) : 0.f;
            const float area_a = (2.f * w2) * (2.f * h2);
            const float iou = inter / (area_t + area_a - inter);
            if (iou > overlap) { overlap = iou; best = a; }   // first-max wins
        }

        skey[t] = (inb && overlap > THRESH) ? (best * G + icy) * G + icx : -1;
    }
    __syncthreads();

    // ---- phase 2: dup-check (last target index wins) + gather + accumulate ----
    #pragma unroll 5
    for (int t = tid; t < total; t += NTHREADS) {
        const int k = skey[t];
        if (k < 0) continue;

        const int gi = t / NT, l = t - gi * NT;
        const int base = gi * NT;
        bool win = true;
        for (int j = l + 1; j < NT; j++)
            if (skey[base + j] == k) { win = false; break; }
        if (!win) continue;

        const int b = gi / 3, g = gi - b * 3;
        const int G = (g == 0) ? 52 : (g == 1) ? 26 : 13;
        const float fG = (float)G;
        const float* out = (g == 0) ? out0 : (g == 1) ? out1 : out2;

        const float* tg = targets + ((size_t)b * NT + l) * 5;   // L1/L2 hit
        const float tx = __ldg(tg + 1) * fG, ty = __ldg(tg + 2) * fG;
        const float tw = __ldg(tg + 3) * fG, th = __ldg(tg + 4) * fG;

        // out index: (((b*NA + best)*G + icy)*G + icx)*NC == (b*NA*G*G + k)*NC
        const float* c = out + ((long long)b * NA * G * G + k) * (long long)NC;
        const float px = __ldg(c + 0), py = __ldg(c + 1);
        const float pw = __ldg(c + 2), ph = __ldg(c + 3);

        const float dx = px - tx;
        const float dy = py - ty;
        const float rw = rsqrtf(pw) - rsqrtf(tw);
        const float rh = rsqrtf(ph) - rsqrtf(th);
        const float contrib = dx * dx + dy * dy + rw * rw + rh * rh;

        // exact fixed-point accumulation (associative -> deterministic)
        const unsigned long long fx =
            (unsigned long long)(long long)((double)contrib * FIXSCALE);
        atomicAdd(&ssum[gi], fx);
        atomicAdd(&scnt[gi], 1);
    }
    __syncthreads();

    // ---- per-group loss, then per-image, then scalar ----
    if (tid < NG) {
        const int n = scnt[tid];
        const float s = (float)((double)(long long)ssum[tid] * (1.0 / FIXSCALE));
        sgl[tid] = (n > 0) ? s / (2.0f * (float)n) : 0.f;
    }
    __syncthreads();

    if (tid < 32) {
        float v = (tid < B) ? (sgl[3 * tid] + sgl[3 * tid + 1] + sgl[3 * tid + 2]) : 0.f;
        #pragma unroll
        for (int off = 16; off > 0; off >>= 1)
            v += __shfl_down_sync(0xffffffffu, v, off);
        if (tid == 0) result[0] = v * invB;
    }
}

extern "C" void kernel_launch(void* const* d_in, const int* in_sizes, int n_in,
                              void* d_out, int out_size)
{
    const float* out0 = (const float*)d_in[0];
    const float* anc0 = (const float*)d_in[1];
    const float* out1 = (const float*)d_in[2];
    const float* anc1 = (const float*)d_in[3];
    const float* out2 = (const float*)d_in[4];
    const float* anc2 = (const float*)d_in[5];
    const float* tgts = (const float*)d_in[6];

    int B = in_sizes[6] / (NT * 5);
    if (B > BMAX) B = BMAX;

    box_loss_single<<<1, NTHREADS>>>(out0, anc0, out1, anc1, out2, anc2, tgts,
                                     (float*)d_out, B, 1.0f / (float)B);
}

// round 6
// speedup vs baseline: 3.6310x; 3.6310x over previous
#include <cuda_runtime.h>

// BoxLoss: 3-scale YOLO box loss. ONE launch, 32 blocks (1 image each, 3
// scale-groups of 64 lanes). Latency-bound: keep the serial chain short AND
// the work spread across 32 SMs (R5 showed 1 block serializes ~5x).
//  - anchors+targets loaded directly (no smem staging, no first sync)
//  - gather of the BEST anchor only, issued before the sync (overlaps
//    sync + dup-check)
//  - tail: partial value doubles as readiness flag (sentinel -1.0f);
//    block 0 polls L2, reduces in fixed lane order, resets sentinels.
//    No atomics, no fences anywhere.

#define NT   50
#define NA   3
#define NC   85
#define BMAX 32
#define THRESH 0.5f

#define M1 -1.f,-1.f,-1.f,-1.f,-1.f,-1.f,-1.f,-1.f
__device__ float g_partials[BMAX] = { M1, M1, M1, M1 };

__device__ __forceinline__ float ld_cg(const float* p) {
    float v;
    asm volatile("ld.global.cg.f32 %0, [%1];" : "=f"(v) : "l"(p) : "memory");
    return v;
}
__device__ __forceinline__ void st_cg(float* p, float v) {
    asm volatile("st.global.cg.f32 [%0], %1;" :: "l"(p), "f"(v) : "memory");
}

__global__ void __launch_bounds__(192, 1)
box_loss_fused(const float* __restrict__ out0, const float* __restrict__ anc0,
               const float* __restrict__ out1, const float* __restrict__ anc1,
               const float* __restrict__ out2, const float* __restrict__ anc2,
               const float* __restrict__ targets,
               float* __restrict__ result, float invB)
{
    const int b   = blockIdx.x;
    const int B   = gridDim.x;
    const int tid = threadIdx.x;
    const int g   = tid >> 6;     // scale group 0..2
    const int l   = tid & 63;

    __shared__ int   skey[3][64];
    __shared__ float wsum[6];
    __shared__ int   wcnt[6];

    const float* out = (g == 0) ? out0 : (g == 1) ? out1 : out2;
    const float* anc = (g == 0) ? anc0 : (g == 1) ? anc1 : anc2;
    const int    G   = (g == 0) ? 52   : (g == 1) ? 26   : 13;

    // ---- all independent global loads issued immediately ----
    const float aw0 = __ldg(anc + 0), ah0 = __ldg(anc + 1);
    const float aw1 = __ldg(anc + 2), ah1 = __ldg(anc + 3);
    const float aw2 = __ldg(anc + 4), ah2 = __ldg(anc + 5);

    float x = 0.f, y = 0.f, w = 0.f, h = 0.f;
    if (l < NT) {
        const float* tg = targets + ((size_t)b * NT + l) * 5;
        x = __ldg(tg + 1); y = __ldg(tg + 2);
        w = __ldg(tg + 3); h = __ldg(tg + 4);
    }

    const bool  valid = (l < NT) && !(x == 0.f && y == 0.f && w == 0.f && h == 0.f);
    const float fG = (float)G;
    const float tx = x * fG, ty = y * fG, tw = w * fG, th = h * fG;
    const float cx = floorf(tx), cy = floorf(ty);
    const int   icx = (int)cx,   icy = (int)cy;
    const bool  inb = valid && icx >= 0 && icx < G && icy >= 0 && icy < G;

    // ---- IoU vs 3 anchors (areas from rect diffs, matching reference) ----
    const float zx = tx - cx - 0.5f, zy = ty - cy - 0.5f;
    const float t0 = zx - tw * 0.5f, t1 = zy - th * 0.5f;
    const float t2 = zx + tw * 0.5f, t3 = zy + th * 0.5f;
    const float area_t = (t2 - t0) * (t3 - t1);

    float overlap = -1.f;
    int   best = 0;
    #pragma unroll
    for (int a = 0; a < NA; a++) {
        const float w2 = ((a == 0) ? aw0 : (a == 1) ? aw1 : aw2) * 0.5f;
        const float h2 = ((a == 0) ? ah0 : (a == 1) ? ah1 : ah2) * 0.5f;
        const float x0 = fmaxf(t0, -w2), y0 = fmaxf(t1, -h2);
        const float x1 = fminf(t2,  w2), y1 = fminf(t3,  h2);
        const float inter  = (x0 < x1 && y0 < y1) ? (x1 - x0) * (y1 - y0) : 0.f;
        const float area_a = (2.f * w2) * (2.f * h2);
        const float iou = inter / (area_t + area_a - inter);
        if (iou > overlap) { overlap = iou; best = a; }   // first-max wins
    }

    const int key = (inb && overlap > THRESH) ? (best * G + icy) * G + icx : -1;
    skey[g][l] = key;

    // ---- speculative gather (best anchor only) before the sync:
    //      DRAM latency overlaps sync + dup-check ----
    float px = 0.f, py = 0.f, pw = 1.f, ph = 1.f;
    if (key >= 0) {
        const float* c = out +
            ((long long)b * NA * G * G + key) * (long long)NC;
        px = __ldg(c + 0); py = __ldg(c + 1);
        pw = __ldg(c + 2); ph = __ldg(c + 3);
    }
    __syncthreads();

    // ---- collision resolution: last target index wins ----
    float sum = 0.f;
    int   cnt = 0;
    if (key >= 0) {
        bool win = true;
        for (int j = l + 1; j < NT; j++)
            if (skey[g][j] == key) { win = false; break; }
        if (win) {
            const float dx = px - tx;
            const float dy = py - ty;
            const float rw = rsqrtf(pw) - rsqrtf(tw);
            const float rh = rsqrtf(ph) - rsqrtf(th);
            sum = dx * dx + dy * dy + rw * rw + rh * rh;
            cnt = 1;
        }
    }

    // ---- warp reduce, per-image combine, publish with sentinel store ----
    #pragma unroll
    for (int off = 16; off > 0; off >>= 1)
        sum += __shfl_down_sync(0xffffffffu, sum, off);
    cnt = __reduce_add_sync(0xffffffffu, cnt);

    const int wid = tid >> 5;
    if ((tid & 31) == 0) { wsum[wid] = sum; wcnt[wid] = cnt; }
    __syncthreads();

    if (tid == 0) {
        float p = 0.f;
        #pragma unroll
        for (int gg = 0; gg < 3; gg++) {
            const float t = wsum[2 * gg] + wsum[2 * gg + 1];
            const int   n = wcnt[2 * gg] + wcnt[2 * gg + 1];
            if (n > 0) p += t / (2.0f * (float)n);
        }
        st_cg(&g_partials[b], p);   // value IS the flag (loss >= 0)
    }

    // ---- block 0, warp 0: poll L2, reduce in fixed lane order ----
    if (b == 0 && tid < 32) {
        const bool mine = (tid < B);
        float v = 0.f;
        for (;;) {
            if (mine) v = ld_cg(&g_partials[tid]);
            const bool pending = mine && (__float_as_uint(v) == 0xBF800000u);
            if (!__any_sync(0xffffffffu, pending)) break;
        }
        float s = mine ? v : 0.f;
        #pragma unroll
        for (int off = 16; off > 0; off >>= 1)
            s += __shfl_down_sync(0xffffffffu, s, off);
        if (mine) st_cg(&g_partials[tid], -1.0f);   // re-arm for next replay
        if (tid == 0) result[0] = s * invB;
    }
}

extern "C" void kernel_launch(void* const* d_in, const int* in_sizes, int n_in,
                              void* d_out, int out_size)
{
    const float* out0 = (const float*)d_in[0];
    const float* anc0 = (const float*)d_in[1];
    const float* out1 = (const float*)d_in[2];
    const float* anc1 = (const float*)d_in[3];
    const float* out2 = (const float*)d_in[4];
    const float* anc2 = (const float*)d_in[5];
    const float* tgts = (const float*)d_in[6];

    int B = in_sizes[6] / (NT * 5);
    if (B > BMAX) B = BMAX;

    box_loss_fused<<<B, 192>>>(out0, anc0, out1, anc1, out2, anc2, tgts,
                               (float*)d_out, 1.0f / (float)B);
}

// round 7
// speedup vs baseline: 4.7308x; 1.3029x over previous
#include <cuda_runtime.h>

// BoxLoss: 3-scale YOLO box loss. ONE launch, 32 blocks (1 image, 3
// independent 64-lane scale groups). Fully latency-oriented:
//  - zero block-wide __syncthreads: groups use named barriers (64 threads)
//  - dup-check via __match_any_sync + 18-key broadcast scan (warp-odd keys)
//  - each group publishes its own loss to a global sentinel slot (st.cg);
//    block 0 polls all 96 slots (3/lane), combines, writes the scalar,
//    and re-arms sentinels. No atomics, no fences anywhere.

#define NT   50
#define NA   3
#define NC   85
#define BMAX 32
#define THRESH 0.5f

#define M1 -1.f,-1.f,-1.f,-1.f,-1.f,-1.f,-1.f,-1.f
__device__ float g_group[BMAX * 3] = { M1,M1,M1,M1, M1,M1,M1,M1, M1,M1,M1,M1 };

__device__ __forceinline__ float ld_cg(const float* p) {
    float v;
    asm volatile("ld.global.cg.f32 %0, [%1];" : "=f"(v) : "l"(p) : "memory");
    return v;
}
__device__ __forceinline__ void st_cg(float* p, float v) {
    asm volatile("st.global.cg.f32 [%0], %1;" :: "l"(p), "f"(v) : "memory");
}
__device__ __forceinline__ void bar_group(int id) {
    asm volatile("bar.sync %0, 64;" :: "r"(id) : "memory");
}

__global__ void __launch_bounds__(192, 1)
box_loss_fused(const float* __restrict__ out0, const float* __restrict__ anc0,
               const float* __restrict__ out1, const float* __restrict__ anc1,
               const float* __restrict__ out2, const float* __restrict__ anc2,
               const float* __restrict__ targets,
               float* __restrict__ result, float invB)
{
    const int b    = blockIdx.x;
    const int B    = gridDim.x;
    const int tid  = threadIdx.x;
    const int g    = tid >> 6;          // scale group 0..2
    const int l    = tid & 63;          // lane in group (== target index)
    const int lane = tid & 31;
    const bool odd = (l >= 32);         // warp-odd of the group

    __shared__ int   skey18[3][18];     // warp-odd keys (targets 32..49)
    __shared__ float wsum[6];
    __shared__ int   wcnt[6];

    const float* out = (g == 0) ? out0 : (g == 1) ? out1 : out2;
    const float* anc = (g == 0) ? anc0 : (g == 1) ? anc1 : anc2;
    const int    G   = (g == 0) ? 52   : (g == 1) ? 26   : 13;

    // ---- all independent global loads issued immediately ----
    const float aw0 = __ldg(anc + 0), ah0 = __ldg(anc + 1);
    const float aw1 = __ldg(anc + 2), ah1 = __ldg(anc + 3);
    const float aw2 = __ldg(anc + 4), ah2 = __ldg(anc + 5);

    float x = 0.f, y = 0.f, w = 0.f, h = 0.f;
    if (l < NT) {
        const float* tg = targets + ((size_t)b * NT + l) * 5;
        x = __ldg(tg + 1); y = __ldg(tg + 2);
        w = __ldg(tg + 3); h = __ldg(tg + 4);
    }

    const bool  valid = (l < NT) && !(x == 0.f && y == 0.f && w == 0.f && h == 0.f);
    const float fG = (float)G;
    const float tx = x * fG, ty = y * fG, tw = w * fG, th = h * fG;
    const float cx = floorf(tx), cy = floorf(ty);
    const int   icx = (int)cx,   icy = (int)cy;
    const bool  inb = valid && icx >= 0 && icx < G && icy >= 0 && icy < G;

    // ---- IoU vs 3 anchors (areas from rect diffs, matching reference) ----
    const float zx = tx - cx - 0.5f, zy = ty - cy - 0.5f;
    const float t0 = zx - tw * 0.5f, t1 = zy - th * 0.5f;
    const float t2 = zx + tw * 0.5f, t3 = zy + th * 0.5f;
    const float area_t = (t2 - t0) * (t3 - t1);

    float overlap = -1.f;
    int   best = 0;
    #pragma unroll
    for (int a = 0; a < NA; a++) {
        const float w2 = ((a == 0) ? aw0 : (a == 1) ? aw1 : aw2) * 0.5f;
        const float h2 = ((a == 0) ? ah0 : (a == 1) ? ah1 : ah2) * 0.5f;
        const float x0 = fmaxf(t0, -w2), y0 = fmaxf(t1, -h2);
        const float x1 = fminf(t2,  w2), y1 = fminf(t3,  h2);
        const float inter  = (x0 < x1 && y0 < y1) ? (x1 - x0) * (y1 - y0) : 0.f;
        const float area_a = (2.f * w2) * (2.f * h2);
        const float iou = inter / (area_t + area_a - inter);
        if (iou > overlap) { overlap = iou; best = a; }   // first-max wins
    }

    const int key = (inb && overlap > THRESH) ? (best * G + icy) * G + icx : -1;
    if (odd && l < NT) skey18[g][l - 32] = key;

    // ---- speculative gather (best anchor only), overlaps barrier+dup ----
    float px = 0.f, py = 0.f, pw = 1.f, ph = 1.f;
    if (key >= 0) {
        const float* c = out + ((long long)b * NA * G * G + key) * (long long)NC;
        px = __ldg(c + 0); py = __ldg(c + 1);
        pw = __ldg(c + 2); ph = __ldg(c + 3);
    }
    bar_group(g + 1);          // skey18 visible within the group

    // ---- collision resolution: last target index wins ----
    // intra-warp: highest lane of equal-key mask wins; warp-odd targets
    // always outrank warp-even, so warp-even also scans the 18 odd keys.
    const unsigned mmask = __match_any_sync(0xffffffffu, key);
    bool win = (key >= 0) && (31 - __clz(mmask) == lane);
    if (!odd && win) {
        bool dup = false;
        #pragma unroll
        for (int j = 0; j < 18; j++)
            dup |= (skey18[g][j] == key);
        win = !dup;
    }

    float sum = 0.f;
    if (win) {
        const float dx = px - tx;
        const float dy = py - ty;
        const float rw = rsqrtf(pw) - rsqrtf(tw);
        const float rh = rsqrtf(ph) - rsqrtf(th);
        sum = dx * dx + dy * dy + rw * rw + rh * rh;
    }
    const int cnt = __popc(__ballot_sync(0xffffffffu, win));

    // ---- warp reduce + intra-group combine + publish ----
    #pragma unroll
    for (int off = 16; off > 0; off >>= 1)
        sum += __shfl_down_sync(0xffffffffu, sum, off);

    const int wid = tid >> 5;
    if (lane == 0) { wsum[wid] = sum; wcnt[wid] = cnt; }
    bar_group(g + 1);

    if (l == 0) {
        const float t = wsum[2 * g] + wsum[2 * g + 1];
        const int   n = wcnt[2 * g] + wcnt[2 * g + 1];
        st_cg(&g_group[b * 3 + g], (n > 0) ? t / (2.0f * (float)n) : 0.f);
    }

    // ---- block 0, warp 0: poll 3 slots/lane, combine, write, re-arm ----
    if (b == 0 && tid < 32) {
        const bool mine = (tid < B);
        float v0 = 0.f, v1 = 0.f, v2 = 0.f;
        float* slot = &g_group[tid * 3];
        for (;;) {
            if (mine) {
                v0 = ld_cg(slot + 0);
                v1 = ld_cg(slot + 1);
                v2 = ld_cg(slot + 2);
            }
            const bool pending = mine &&
                ((__float_as_uint(v0) == 0xBF800000u) |
                 (__float_as_uint(v1) == 0xBF800000u) |
                 (__float_as_uint(v2) == 0xBF800000u));
            if (!__any_sync(0xffffffffu, pending)) break;
        }
        float s = mine ? (v0 + v1 + v2) : 0.f;
        #pragma unroll
        for (int off = 16; off > 0; off >>= 1)
            s += __shfl_down_sync(0xffffffffu, s, off);
        if (mine) {                       // re-arm sentinels for next replay
            st_cg(slot + 0, -1.0f);
            st_cg(slot + 1, -1.0f);
            st_cg(slot + 2, -1.0f);
        }
        if (tid == 0) result[0] = s * invB;
    }
}

extern "C" void kernel_launch(void* const* d_in, const int* in_sizes, int n_in,
                              void* d_out, int out_size)
{
    const float* out0 = (const float*)d_in[0];
    const float* anc0 = (const float*)d_in[1];
    const float* out1 = (const float*)d_in[2];
    const float* anc1 = (const float*)d_in[3];
    const float* out2 = (const float*)d_in[4];
    const float* anc2 = (const float*)d_in[5];
    const float* tgts = (const float*)d_in[6];

    int B = in_sizes[6] / (NT * 5);
    if (B > BMAX) B = BMAX;

    box_loss_fused<<<B, 192>>>(out0, anc0, out1, anc1, out2, anc2, tgts,
                               (float*)d_out, 1.0f / (float)B);
}